// round 13
// baseline (speedup 1.0000x reference)
#include <cuda_runtime.h>
#include <cuda_fp16.h>
#include <cstdint>

#define NN 100000
#define NE 1600000
#define EMB 64
#define EPS 1e-5f
#define EDGE_GRID 2048
#define NTILES (NE / 128)
#define FUSED_GRID 444

// dynamic smem layout for fused kernel (bytes)
#define OFF_AS    0        // As[128][68] f32 (padded row-major, tf32-converted)   34816
#define OFF_BF    34816    // B frag-major [64 slabs][32 lanes][2] f32             16384
#define OFF_SRC   51200    // 128 int
#define OFF_DST   51712    // 128 int
#define OFF_SC    52224    // bn1 scale (64 f32)
#define OFF_SH    52480    // bn1 shift' (64 f32, includes mb1)
#define OFF_B2    52736    // mb2 (64 f32)
#define OFF_RED   52992    // stats reduction 128 f32
#define SMEM_FUSED 53504

// ---------------- scratch (device globals: allocation-free contract) ----------------
__device__ __align__(256) float g_h[NN * EMB];
__device__ __align__(256) float g_P[NN * EMB];     // reused as T1 (upd layer-1 out)
__device__ __align__(256) float g_Q[NN * EMB];     // reused as U2 (upd layer-2 out)
__device__ __align__(256) __half g_P16[NN * EMB];  // fp16 P/Q: sole edge-phase inputs
__device__ __align__(256) __half g_Q16[NN * EMB];
__device__ __align__(256) float g_aggr[NN * EMB];
__device__ __align__(256) __half g_X2h[(size_t)NE * EMB];   // fp16 X2
__device__ float g_stat[4 * 2 * EMB];   // per BN stage: [sum(64) | sumsq(64)]
__device__ float g_bn[4 * 2 * EMB];     // per BN stage: [scale(64) | shift(64)]
__device__ int   g_is64;

// ---------------- helpers ----------------
__device__ __forceinline__ uint32_t f2tf32(float f) {
    uint32_t o;
    asm("cvt.rna.tf32.f32 %0, %1;" : "=r"(o) : "f"(f));
    return o;
}
__device__ __forceinline__ void mma_tf32(float* c, const uint32_t* a, uint32_t b0, uint32_t b1) {
    asm volatile(
        "mma.sync.aligned.m16n8k8.row.col.f32.tf32.tf32.f32 "
        "{%0,%1,%2,%3}, {%4,%5,%6,%7}, {%8,%9}, {%0,%1,%2,%3};"
        : "+f"(c[0]), "+f"(c[1]), "+f"(c[2]), "+f"(c[3])
        : "r"(a[0]), "r"(a[1]), "r"(a[2]), "r"(a[3]), "r"(b0), "r"(b1));
}

// ---------------- int32/int64 edge-index detection ----------------
__global__ void k_detect(const unsigned int* ei_words) {
    __shared__ int any;
    if (threadIdx.x == 0) any = 0;
    __syncthreads();
    for (int i = threadIdx.x; i < 2048; i += blockDim.x)
        if (ei_words[2 * i + 1] != 0u) atomicOr(&any, 1);
    __syncthreads();
    if (threadIdx.x == 0) g_is64 = any ? 0 : 1;
}
__device__ __forceinline__ int ld_idx(const void* ei, long i, int is64) {
    if (is64) return (int)((const long long*)ei)[i];
    return ((const int*)ei)[i];
}

// ---------------- node embedding ----------------
__global__ void __launch_bounds__(256) k_node_embed(
    const float* __restrict__ pos, const float* __restrict__ vel,
    const float* __restrict__ Win, const float* __restrict__ bin)
{
    int n = blockIdx.x * blockDim.x + threadIdx.x;
    if (n >= NN) return;
    float p0 = pos[2 * n], p1 = pos[2 * n + 1];
    float v0 = vel[2 * n], v1 = vel[2 * n + 1];
    float4* out = (float4*)(g_h + (size_t)n * EMB);
#pragma unroll
    for (int c4 = 0; c4 < 16; c4++) {
        float4 w0 = ((const float4*)(Win + 0 * EMB))[c4];
        float4 w1 = ((const float4*)(Win + 1 * EMB))[c4];
        float4 w2 = ((const float4*)(Win + 2 * EMB))[c4];
        float4 w3 = ((const float4*)(Win + 3 * EMB))[c4];
        float4 b  = ((const float4*)bin)[c4];
        float4 o;
        o.x = fmaf(p0, w0.x, fmaf(p1, w1.x, fmaf(v0, w2.x, fmaf(v1, w3.x, b.x))));
        o.y = fmaf(p0, w0.y, fmaf(p1, w1.y, fmaf(v0, w2.y, fmaf(v1, w3.y, b.y))));
        o.z = fmaf(p0, w0.z, fmaf(p1, w1.z, fmaf(v0, w2.z, fmaf(v1, w3.z, b.z))));
        o.w = fmaf(p0, w0.w, fmaf(p1, w1.w, fmaf(v0, w2.w, fmaf(v1, w3.w, b.w))));
        out[c4] = o;
    }
}

// ---------------- generic rows x 64 @ 64 x 64 GEMM with fused epilogues ----------------
// BNIN: relu(bn) on input load  ACCUM: out += (needs OUT32)  BIAS: +bias[col]
// STATS: sum/sumsq  SHADOW: write fp16 copy  OUT32: write fp32 out
template <bool BNIN, bool ACCUM, bool BIAS, bool STATS, bool SHADOW, bool OUT32>
__global__ void __launch_bounds__(256) k_gemm64(
    const float* __restrict__ X, const float* __restrict__ W,
    const float* __restrict__ bias, const float* __restrict__ scale,
    const float* __restrict__ shift, float* __restrict__ out,
    __half* __restrict__ shadow, float* __restrict__ stat, int rows)
{
    __shared__ float Xs[128 * EMB];
    __shared__ float Ws[EMB * EMB];
    const int tid = threadIdx.x;
    const long rowbase = (long)blockIdx.x * 128;
    long vr = (long)rows - rowbase;
    const int validRows = (vr > 128) ? 128 : (int)vr;

    {
        const float4* Wg = (const float4*)W;
        float4* Wsv = (float4*)Ws;
        for (int i = tid; i < 1024; i += 256) Wsv[i] = Wg[i];
    }
    {
        const float4* Xg = (const float4*)(X + rowbase * EMB);
        float4* Xsv = (float4*)Xs;
        for (int i = tid; i < 2048; i += 256) {
            int r = i >> 4;
            float4 v;
            if (r < validRows) v = Xg[i];
            else v = make_float4(0.f, 0.f, 0.f, 0.f);
            if (BNIN) {
                int k4 = i & 15;
                float4 sc = ((const float4*)scale)[k4];
                float4 sh = ((const float4*)shift)[k4];
                v.x = fmaxf(fmaf(v.x, sc.x, sh.x), 0.f);
                v.y = fmaxf(fmaf(v.y, sc.y, sh.y), 0.f);
                v.z = fmaxf(fmaf(v.z, sc.z, sh.z), 0.f);
                v.w = fmaxf(fmaf(v.w, sc.w, sh.w), 0.f);
            }
            Xsv[i] = v;
        }
    }
    __syncthreads();

    const int tr = tid >> 4, tc = tid & 15;
    const int r0 = tr * 8, c0 = tc * 4;
    float acc[8][4];
#pragma unroll
    for (int i = 0; i < 8; i++)
#pragma unroll
        for (int j = 0; j < 4; j++) acc[i][j] = 0.f;

#pragma unroll 16
    for (int k = 0; k < EMB; k++) {
        float4 b = *(const float4*)(Ws + k * EMB + c0);
#pragma unroll
        for (int i = 0; i < 8; i++) {
            float a = Xs[(r0 + i) * EMB + k];
            acc[i][0] = fmaf(a, b.x, acc[i][0]);
            acc[i][1] = fmaf(a, b.y, acc[i][1]);
            acc[i][2] = fmaf(a, b.z, acc[i][2]);
            acc[i][3] = fmaf(a, b.w, acc[i][3]);
        }
    }

    float4 bi = make_float4(0.f, 0.f, 0.f, 0.f);
    if (BIAS) bi = ((const float4*)bias)[tc];
    float ls[4] = {0.f, 0.f, 0.f, 0.f}, lq[4] = {0.f, 0.f, 0.f, 0.f};
#pragma unroll
    for (int i = 0; i < 8; i++) {
        int r = r0 + i;
        if (r < validRows) {
            float4 o;
            o.x = acc[i][0] + bi.x; o.y = acc[i][1] + bi.y;
            o.z = acc[i][2] + bi.z; o.w = acc[i][3] + bi.w;
            if (OUT32) {
                float4* op = (float4*)(out + (rowbase + r) * EMB + c0);
                if (ACCUM) {
                    float4 pv = *op;
                    o.x += pv.x; o.y += pv.y; o.z += pv.z; o.w += pv.w;
                }
                *op = o;
            }
            if (SHADOW) {
                __half* hp = shadow + (rowbase + r) * EMB + c0;
                *(__half2*)(hp)     = __floats2half2_rn(o.x, o.y);
                *(__half2*)(hp + 2) = __floats2half2_rn(o.z, o.w);
            }
            if (STATS) {
                ls[0] += o.x; lq[0] += o.x * o.x;
                ls[1] += o.y; lq[1] += o.y * o.y;
                ls[2] += o.z; lq[2] += o.z * o.z;
                ls[3] += o.w; lq[3] += o.w * o.w;
            }
        }
    }

    if (STATS) {
        __syncthreads();
        float* red = Xs;
#pragma unroll
        for (int j = 0; j < 4; j++) {
            red[tr * EMB + c0 + j]        = ls[j];
            red[1024 + tr * EMB + c0 + j] = lq[j];
        }
        __syncthreads();
        if (tid < EMB) {
            float s = 0.f, q = 0.f;
#pragma unroll
            for (int t = 0; t < 16; t++) {
                s += red[t * EMB + tid];
                q += red[1024 + t * EMB + tid];
            }
            atomicAdd(stat + tid, s);
            atomicAdd(stat + EMB + tid, q);
        }
    }
}

// ---------------- BN1 stats from fp16 P/Q (no X1 materialization) ----------------
__global__ void __launch_bounds__(256) k_edge_stats1(const void* ei, const float* __restrict__ mb1) {
    const int gid = blockIdx.x * 256 + threadIdx.x;
    const int lane = gid & 15;
    const int c0 = lane * 4;
    const int estride = (EDGE_GRID * 256) >> 4;
    const int is64 = g_is64;
    float4 b = ((const float4*)mb1)[lane];
    float s0 = 0, s1 = 0, s2 = 0, s3 = 0, q0 = 0, q1 = 0, q2 = 0, q3 = 0;
    for (int e = gid >> 4; e < NE; e += estride) {
        int src = ld_idx(ei, e, is64);
        int dst = ld_idx(ei, (long)NE + e, is64);
        uint2 pw = *(const uint2*)(g_P16 + (size_t)dst * EMB + c0);
        uint2 qw = *(const uint2*)(g_Q16 + (size_t)src * EMB + c0);
        float2 p01 = __half22float2(*(__half2*)&pw.x);
        float2 p23 = __half22float2(*(__half2*)&pw.y);
        float2 q01 = __half22float2(*(__half2*)&qw.x);
        float2 q23 = __half22float2(*(__half2*)&qw.y);
        float x0 = p01.x + q01.x + b.x, x1 = p01.y + q01.y + b.y;
        float x2 = p23.x + q23.x + b.z, x3 = p23.y + q23.y + b.w;
        s0 += x0; q0 += x0 * x0;
        s1 += x1; q1 += x1 * x1;
        s2 += x2; q2 += x2 * x2;
        s3 += x3; q3 += x3 * x3;
    }
    __shared__ float red[128];
    if (threadIdx.x < 128) red[threadIdx.x] = 0.f;
    __syncthreads();
    atomicAdd(&red[c0 + 0], s0); atomicAdd(&red[c0 + 1], s1);
    atomicAdd(&red[c0 + 2], s2); atomicAdd(&red[c0 + 3], s3);
    atomicAdd(&red[64 + c0 + 0], q0); atomicAdd(&red[64 + c0 + 1], q1);
    atomicAdd(&red[64 + c0 + 2], q2); atomicAdd(&red[64 + c0 + 3], q3);
    __syncthreads();
    if (threadIdx.x < 128) atomicAdd(&g_stat[threadIdx.x], red[threadIdx.x]);
}

// ---------------- fused edge GEMM via mma.sync tf32, fp16 gather, fp16 X2 out ----------------
// X2[tile] = relu(bn1'(P[dst]+Q[src])) @ mW2 + mb2; BN2 stats computed on the
// fp16-ROUNDED values so bn2 is exactly the BN of the stored X2.
__global__ void __launch_bounds__(256) k_edge_fused(const void* ei, const float* __restrict__ mW2,
                                                    const float* __restrict__ mb2) {
    extern __shared__ char smem[];
    float* As   = (float*)(smem + OFF_AS);      // [128][68]
    float* Bf   = (float*)(smem + OFF_BF);      // [(ks*8+nt)*32 + lane][2]
    int* s_src  = (int*)(smem + OFF_SRC);
    int* s_dst  = (int*)(smem + OFF_DST);
    float* sc_s = (float*)(smem + OFF_SC);
    float* sh_s = (float*)(smem + OFF_SH);
    float* b2_s = (float*)(smem + OFF_B2);
    float* red  = (float*)(smem + OFF_RED);

    const int tid = threadIdx.x;
    const int wid = tid >> 5;
    const int lane = tid & 31;
    const int gidq = lane >> 2;
    const int tig = lane & 3;
    const int is64 = g_is64;

    for (int i = tid; i < 2048; i += 256) {
        int slab = i >> 5, ln = i & 31;
        int ks = slab >> 3, nt = slab & 7;
        int g = ln >> 2, t = ln & 3;
        uint32_t b0 = f2tf32(mW2[(ks * 8 + t) * 64 + nt * 8 + g]);
        uint32_t b1 = f2tf32(mW2[(ks * 8 + t + 4) * 64 + nt * 8 + g]);
        ((uint32_t*)Bf)[2 * i]     = b0;
        ((uint32_t*)Bf)[2 * i + 1] = b1;
    }
    if (tid < EMB) {
        sc_s[tid] = g_bn[tid];
        sh_s[tid] = g_bn[EMB + tid];
        b2_s[tid] = mb2[tid];
    }
    if (tid < 128) red[tid] = 0.f;
    __syncthreads();

    float st_s[16], st_q[16];
#pragma unroll
    for (int i = 0; i < 16; i++) { st_s[i] = 0.f; st_q[i] = 0.f; }

    for (int tile = blockIdx.x; tile < NTILES; tile += gridDim.x) {
        if (tid < 128) {
            s_src[tid] = ld_idx(ei, (long)tile * 128 + tid, is64);
            s_dst[tid] = ld_idx(ei, (long)NE + (long)tile * 128 + tid, is64);
        }
        __syncthreads();

        // gather fp16 P,Q + bn1' + relu + tf32-cvt -> As[row][c] (row stride 68)
        {
            const int row = tid >> 1, half = tid & 1;
            const uint4* Pp = (const uint4*)(g_P16 + (size_t)s_dst[row] * EMB) + half * 4;
            const uint4* Qp = (const uint4*)(g_Q16 + (size_t)s_src[row] * EMB) + half * 4;
            uint32_t* dstw = (uint32_t*)(As + row * 68 + half * 32);
#pragma unroll
            for (int f2 = 0; f2 < 4; f2++) {
                uint4 pw = Pp[f2], qw = Qp[f2];
                int cg = half * 32 + f2 * 8;
                float4 sc0 = *(const float4*)(sc_s + cg);
                float4 sh0 = *(const float4*)(sh_s + cg);
                float4 sc1 = *(const float4*)(sc_s + cg + 4);
                float4 sh1 = *(const float4*)(sh_s + cg + 4);
                float2 p01 = __half22float2(*(__half2*)&pw.x);
                float2 p23 = __half22float2(*(__half2*)&pw.y);
                float2 p45 = __half22float2(*(__half2*)&pw.z);
                float2 p67 = __half22float2(*(__half2*)&pw.w);
                float2 q01 = __half22float2(*(__half2*)&qw.x);
                float2 q23 = __half22float2(*(__half2*)&qw.y);
                float2 q45 = __half22float2(*(__half2*)&qw.z);
                float2 q67 = __half22float2(*(__half2*)&qw.w);
                uint4 o1, o2;
                o1.x = f2tf32(fmaxf(fmaf(p01.x + q01.x, sc0.x, sh0.x), 0.f));
                o1.y = f2tf32(fmaxf(fmaf(p01.y + q01.y, sc0.y, sh0.y), 0.f));
                o1.z = f2tf32(fmaxf(fmaf(p23.x + q23.x, sc0.z, sh0.z), 0.f));
                o1.w = f2tf32(fmaxf(fmaf(p23.y + q23.y, sc0.w, sh0.w), 0.f));
                o2.x = f2tf32(fmaxf(fmaf(p45.x + q45.x, sc1.x, sh1.x), 0.f));
                o2.y = f2tf32(fmaxf(fmaf(p45.y + q45.y, sc1.y, sh1.y), 0.f));
                o2.z = f2tf32(fmaxf(fmaf(p67.x + q67.x, sc1.z, sh1.z), 0.f));
                o2.w = f2tf32(fmaxf(fmaf(p67.y + q67.y, sc1.w, sh1.w), 0.f));
                *(uint4*)(dstw + f2 * 8)     = o1;
                *(uint4*)(dstw + f2 * 8 + 4) = o2;
            }
        }
        __syncthreads();

        uint32_t a[8][4];
        {
            const uint32_t* Ab = (const uint32_t*)As + (wid * 16 + gidq) * 68 + tig;
#pragma unroll
            for (int ks = 0; ks < 8; ks++) {
                a[ks][0] = Ab[ks * 8];
                a[ks][1] = Ab[ks * 8 + 8 * 68];
                a[ks][2] = Ab[ks * 8 + 4];
                a[ks][3] = Ab[ks * 8 + 8 * 68 + 4];
            }
        }

        const int row0 = tile * 128 + wid * 16 + gidq;
#pragma unroll
        for (int nt = 0; nt < 8; nt++) {
            float c[4] = {0.f, 0.f, 0.f, 0.f};
#pragma unroll
            for (int ks = 0; ks < 8; ks++) {
                uint2 b = *(const uint2*)((const uint32_t*)Bf + ((ks * 8 + nt) * 32 + lane) * 2);
                mma_tf32(c, a[ks], b.x, b.y);
            }
            int col = nt * 8 + tig * 2;
            float b0 = b2_s[col], b1 = b2_s[col + 1];
            // round to fp16, store, and take stats on the ROUNDED values
            __half2 h01 = __floats2half2_rn(c[0] + b0, c[1] + b1);   // row0
            __half2 h23 = __floats2half2_rn(c[2] + b0, c[3] + b1);   // row0+8
            *(__half2*)(g_X2h + (size_t)row0 * EMB + col)       = h01;
            *(__half2*)(g_X2h + (size_t)(row0 + 8) * EMB + col) = h23;
            float2 r01 = __half22float2(h01);
            float2 r23 = __half22float2(h23);
            st_s[nt * 2]     += r01.x + r23.x;
            st_s[nt * 2 + 1] += r01.y + r23.y;
            st_q[nt * 2]     += r01.x * r01.x + r23.x * r23.x;
            st_q[nt * 2 + 1] += r01.y * r01.y + r23.y * r23.y;
        }
        __syncthreads();
    }

#pragma unroll
    for (int nt = 0; nt < 8; nt++) {
        int col = nt * 8 + tig * 2;
        atomicAdd(&red[col],          st_s[nt * 2]);
        atomicAdd(&red[col + 1],      st_s[nt * 2 + 1]);
        atomicAdd(&red[64 + col],     st_q[nt * 2]);
        atomicAdd(&red[64 + col + 1], st_q[nt * 2 + 1]);
    }
    __syncthreads();
    if (tid < 128) atomicAdd(&g_stat[128 + tid], red[tid]);
}

// ---------------- edge scatter: aggr[dst] += relu(bn2(X2[e])), fp16 reads, red.v4 ----------------
__global__ void __launch_bounds__(256) k_edge_scatter(const void* ei) {
    const int gid = blockIdx.x * 256 + threadIdx.x;
    const int lane = gid & 15;
    const int c0 = lane * 4;
    const int estride = (EDGE_GRID * 256) >> 4;
    const int is64 = g_is64;
    float4 sc = *(const float4*)(g_bn + 128 + c0);
    float4 sh = *(const float4*)(g_bn + 128 + 64 + c0);
#pragma unroll 2
    for (int e = gid >> 4; e < NE; e += estride) {
        int dst = ld_idx(ei, (long)NE + e, is64);
        uint2 xw = *(const uint2*)(g_X2h + (size_t)e * EMB + c0);
        float2 x01 = __half22float2(*(__half2*)&xw.x);
        float2 x23 = __half22float2(*(__half2*)&xw.y);
        float y0 = fmaxf(fmaf(x01.x, sc.x, sh.x), 0.f);
        float y1 = fmaxf(fmaf(x01.y, sc.y, sh.y), 0.f);
        float y2 = fmaxf(fmaf(x23.x, sc.z, sh.z), 0.f);
        float y3 = fmaxf(fmaf(x23.y, sc.w, sh.w), 0.f);
        float* a = g_aggr + (size_t)dst * EMB + c0;
        asm volatile("red.global.add.v4.f32 [%0], {%1, %2, %3, %4};"
                     :: "l"(a), "f"(y0), "f"(y1), "f"(y2), "f"(y3) : "memory");
    }
}

// ---------------- BN finalize ----------------
__global__ void k_finalize(int stage, float invcnt,
                           const float* __restrict__ gamma, const float* __restrict__ beta,
                           const float* __restrict__ bias) {
    int c = threadIdx.x;
    if (c >= EMB) return;
    float mu = g_stat[stage * 128 + c] * invcnt;
    float var = g_stat[stage * 128 + EMB + c] * invcnt - mu * mu;
    float sc = gamma[c] * rsqrtf(var + EPS);
    float sh = beta[c] - mu * sc;
    if (bias) sh += bias[c] * sc;   // fold linear bias into shift
    g_bn[stage * 128 + c] = sc;
    g_bn[stage * 128 + EMB + c] = sh;
}

// ---------------- final prediction ----------------
__global__ void __launch_bounds__(256) k_pred(const float* __restrict__ Wp,
                                              const float* __restrict__ bp,
                                              float* __restrict__ out) {
    int n = blockIdx.x * blockDim.x + threadIdx.x;
    if (n >= NN) return;
    float acc = bp[0];
    const float4* u = (const float4*)(g_Q + (size_t)n * EMB);
#pragma unroll
    for (int c4 = 0; c4 < 16; c4++) {
        float4 v  = u[c4];
        float4 sc = ((const float4*)(g_bn + 3 * 128))[c4];
        float4 sh = ((const float4*)(g_bn + 3 * 128 + 64))[c4];
        float4 w  = ((const float4*)Wp)[c4];
        acc = fmaf(fmaxf(fmaf(v.x, sc.x, sh.x), 0.f), w.x, acc);
        acc = fmaf(fmaxf(fmaf(v.y, sc.y, sh.y), 0.f), w.y, acc);
        acc = fmaf(fmaxf(fmaf(v.z, sc.z, sh.z), 0.f), w.z, acc);
        acc = fmaf(fmaxf(fmaf(v.w, sc.w, sh.w), 0.f), w.w, acc);
    }
    out[n] = acc;
}

// ---------------- launch ----------------
extern "C" void kernel_launch(void* const* d_in, const int* in_sizes, int n_in,
                              void* d_out, int out_size) {
    const float* pos = (const float*)d_in[0];
    const float* vel = (const float*)d_in[1];
    const void*  ei  = d_in[2];
    const float* Win = (const float*)d_in[3];
    const float* bin = (const float*)d_in[4];
    const float* mW1 = (const float*)d_in[5];
    const float* mb1 = (const float*)d_in[6];
    const float* mg1 = (const float*)d_in[7];
    const float* mB1 = (const float*)d_in[8];
    const float* mW2 = (const float*)d_in[9];
    const float* mb2 = (const float*)d_in[10];
    const float* mg2 = (const float*)d_in[11];
    const float* mB2 = (const float*)d_in[12];
    const float* uW1 = (const float*)d_in[13];
    const float* ub1 = (const float*)d_in[14];
    const float* ug1 = (const float*)d_in[15];
    const float* uB1 = (const float*)d_in[16];
    const float* uW2 = (const float*)d_in[17];
    const float* ub2 = (const float*)d_in[18];
    const float* ug2 = (const float*)d_in[19];
    const float* uB2 = (const float*)d_in[20];
    const float* Wp  = (const float*)d_in[21];
    const float* bp  = (const float*)d_in[22];
    float* out = (float*)d_out;

    static bool attr_set = false;
    if (!attr_set) {
        cudaFuncSetAttribute(k_edge_fused, cudaFuncAttributeMaxDynamicSharedMemorySize, SMEM_FUSED);
        attr_set = true;
    }

    float *pH, *pP, *pQ, *pAg, *pStat, *pBn;
    __half *pP16, *pQ16;
    cudaGetSymbolAddress((void**)&pH, g_h);
    cudaGetSymbolAddress((void**)&pP, g_P);
    cudaGetSymbolAddress((void**)&pQ, g_Q);
    cudaGetSymbolAddress((void**)&pP16, g_P16);
    cudaGetSymbolAddress((void**)&pQ16, g_Q16);
    cudaGetSymbolAddress((void**)&pAg, g_aggr);
    cudaGetSymbolAddress((void**)&pStat, g_stat);
    cudaGetSymbolAddress((void**)&pBn, g_bn);

    cudaMemsetAsync(pAg, 0, (size_t)NN * EMB * sizeof(float));
    cudaMemsetAsync(pStat, 0, 4 * 2 * EMB * sizeof(float));

    const int GN = (NN + 127) / 128;

    k_detect<<<1, 256>>>((const unsigned int*)ei);
    k_node_embed<<<(NN + 255) / 256, 256>>>(pos, vel, Win, bin);

    // P16 = h @ mW1_top ; Q16 = h @ mW1_bot  (fp16 only — sole edge-phase inputs)
    k_gemm64<false, false, false, false, true, false><<<GN, 256>>>(pH, mW1, nullptr, nullptr, nullptr, nullptr, pP16, nullptr, NN);
    k_gemm64<false, false, false, false, true, false><<<GN, 256>>>(pH, mW1 + 64 * 64, nullptr, nullptr, nullptr, nullptr, pQ16, nullptr, NN);

    // BN1 stats from fp16 P/Q, finalize with mb1 folded into shift
    k_edge_stats1<<<EDGE_GRID, 256>>>(ei, mb1);
    k_finalize<<<1, 64>>>(0, 1.0f / (float)NE, mg1, mB1, mb1);

    // fused: X2(fp16) = relu(bn1'(P16[dst]+Q16[src])) @ mW2 + mb2 (mma.sync tf32) + BN2 stats
    k_edge_fused<<<FUSED_GRID, 256, SMEM_FUSED>>>(ei, mW2, mb2);
    k_finalize<<<1, 64>>>(1, 1.0f / (float)NE, mg2, mB2, nullptr);

    // aggr = segment_sum(relu(bn2(X2)), dst)
    k_edge_scatter<<<EDGE_GRID, 256>>>(ei);

    // update MLP layer 1: T1 = h @ uW1_top + aggr @ uW1_bot + ub1, BN3 stats
    k_gemm64<false, false, false, false, false, true><<<GN, 256>>>(pH, uW1, nullptr, nullptr, nullptr, pP, nullptr, nullptr, NN);
    k_gemm64<false, true, true, true, false, true><<<GN, 256>>>(pAg, uW1 + 64 * 64, ub1, nullptr, nullptr, pP, nullptr, pStat + 256, NN);
    k_finalize<<<1, 64>>>(2, 1.0f / (float)NN, ug1, uB1, nullptr);

    // update MLP layer 2: U2 = relu(bn3(T1)) @ uW2 + ub2, BN4 stats
    k_gemm64<true, false, true, true, false, true><<<GN, 256>>>(pP, uW2, ub2, pBn + 256, pBn + 256 + 64, pQ, nullptr, pStat + 384, NN);
    k_finalize<<<1, 64>>>(3, 1.0f / (float)NN, ug2, uB2, nullptr);

    // out = relu(bn4(U2)) @ W_pred + b_pred
    k_pred<<<(NN + 255) / 256, 256>>>(Wp, bp, out);
}

// round 14
// speedup vs baseline: 1.3801x; 1.3801x over previous
#include <cuda_runtime.h>
#include <cuda_fp16.h>
#include <cstdint>

#define NN 100000
#define NE 1600000
#define EMB 64
#define EPS 1e-5f
#define EDGE_GRID 2048
#define NTILES (NE / 128)
#define FUSED_GRID 444

// dynamic smem layout for fused kernel (bytes)
#define OFF_AS    0        // As[128][68] f32 (padded row-major, tf32-converted)   34816
#define OFF_BF    34816    // B frag-major [64 slabs][32 lanes][2] f32             16384
#define OFF_SRC   51200    // 128 int
#define OFF_DST   51712    // 128 int
#define OFF_SC    52224    // bn1 scale (64 f32)
#define OFF_SH    52480    // bn1 shift' (64 f32, includes mb1)
#define OFF_B2    52736    // mb2 (64 f32)
#define OFF_RED   52992    // stats reduction 128 f32
#define SMEM_FUSED 53504

// ---------------- scratch (device globals: allocation-free contract) ----------------
__device__ __align__(256) float g_h[NN * EMB];
__device__ __align__(256) float g_P[NN * EMB];     // reused as T1 (upd layer-1 out)
__device__ __align__(256) float g_Q[NN * EMB];     // reused as U2 (upd layer-2 out)
__device__ __align__(256) __half g_P16[NN * EMB];  // fp16 P/Q: sole edge-phase inputs
__device__ __align__(256) __half g_Q16[NN * EMB];
__device__ __align__(256) float g_aggr[NN * EMB];
__device__ __align__(256) __half g_X2h[(size_t)NE * EMB];   // fp16 X2
__device__ float g_stat[4 * 2 * EMB];   // per BN stage: [sum(64) | sumsq(64)]
__device__ float g_bn[4 * 2 * EMB];     // per BN stage: [scale(64) | shift(64)]
__device__ int   g_is64;

// ---------------- helpers ----------------
__device__ __forceinline__ uint32_t f2tf32(float f) {
    uint32_t o;
    asm("cvt.rna.tf32.f32 %0, %1;" : "=r"(o) : "f"(f));
    return o;
}
__device__ __forceinline__ void mma_tf32(float* c, const uint32_t* a, uint32_t b0, uint32_t b1) {
    asm volatile(
        "mma.sync.aligned.m16n8k8.row.col.f32.tf32.tf32.f32 "
        "{%0,%1,%2,%3}, {%4,%5,%6,%7}, {%8,%9}, {%0,%1,%2,%3};"
        : "+f"(c[0]), "+f"(c[1]), "+f"(c[2]), "+f"(c[3])
        : "r"(a[0]), "r"(a[1]), "r"(a[2]), "r"(a[3]), "r"(b0), "r"(b1));
}

// ---------------- int32/int64 edge-index detection ----------------
__global__ void k_detect(const unsigned int* ei_words) {
    __shared__ int any;
    if (threadIdx.x == 0) any = 0;
    __syncthreads();
    for (int i = threadIdx.x; i < 2048; i += blockDim.x)
        if (ei_words[2 * i + 1] != 0u) atomicOr(&any, 1);
    __syncthreads();
    if (threadIdx.x == 0) g_is64 = any ? 0 : 1;
}
__device__ __forceinline__ int ld_idx(const void* ei, long i, int is64) {
    if (is64) return (int)((const long long*)ei)[i];
    return ((const int*)ei)[i];
}

// ---------------- node embedding ----------------
__global__ void __launch_bounds__(256) k_node_embed(
    const float* __restrict__ pos, const float* __restrict__ vel,
    const float* __restrict__ Win, const float* __restrict__ bin)
{
    int n = blockIdx.x * blockDim.x + threadIdx.x;
    if (n >= NN) return;
    float p0 = pos[2 * n], p1 = pos[2 * n + 1];
    float v0 = vel[2 * n], v1 = vel[2 * n + 1];
    float4* out = (float4*)(g_h + (size_t)n * EMB);
#pragma unroll
    for (int c4 = 0; c4 < 16; c4++) {
        float4 w0 = ((const float4*)(Win + 0 * EMB))[c4];
        float4 w1 = ((const float4*)(Win + 1 * EMB))[c4];
        float4 w2 = ((const float4*)(Win + 2 * EMB))[c4];
        float4 w3 = ((const float4*)(Win + 3 * EMB))[c4];
        float4 b  = ((const float4*)bin)[c4];
        float4 o;
        o.x = fmaf(p0, w0.x, fmaf(p1, w1.x, fmaf(v0, w2.x, fmaf(v1, w3.x, b.x))));
        o.y = fmaf(p0, w0.y, fmaf(p1, w1.y, fmaf(v0, w2.y, fmaf(v1, w3.y, b.y))));
        o.z = fmaf(p0, w0.z, fmaf(p1, w1.z, fmaf(v0, w2.z, fmaf(v1, w3.z, b.z))));
        o.w = fmaf(p0, w0.w, fmaf(p1, w1.w, fmaf(v0, w2.w, fmaf(v1, w3.w, b.w))));
        out[c4] = o;
    }
}

// ---------------- generic rows x 64 @ 64 x 64 GEMM with fused epilogues ----------------
// BNIN: relu(bn) on input load  ACCUM: out += (needs OUT32)  BIAS: +bias[col]
// STATS: sum/sumsq  SHADOW: write fp16 copy  OUT32: write fp32 out
template <bool BNIN, bool ACCUM, bool BIAS, bool STATS, bool SHADOW, bool OUT32>
__global__ void __launch_bounds__(256) k_gemm64(
    const float* __restrict__ X, const float* __restrict__ W,
    const float* __restrict__ bias, const float* __restrict__ scale,
    const float* __restrict__ shift, float* __restrict__ out,
    __half* __restrict__ shadow, float* __restrict__ stat, int rows)
{
    __shared__ float Xs[128 * EMB];
    __shared__ float Ws[EMB * EMB];
    const int tid = threadIdx.x;
    const long rowbase = (long)blockIdx.x * 128;
    long vr = (long)rows - rowbase;
    const int validRows = (vr > 128) ? 128 : (int)vr;

    {
        const float4* Wg = (const float4*)W;
        float4* Wsv = (float4*)Ws;
        for (int i = tid; i < 1024; i += 256) Wsv[i] = Wg[i];
    }
    {
        const float4* Xg = (const float4*)(X + rowbase * EMB);
        float4* Xsv = (float4*)Xs;
        for (int i = tid; i < 2048; i += 256) {
            int r = i >> 4;
            float4 v;
            if (r < validRows) v = Xg[i];
            else v = make_float4(0.f, 0.f, 0.f, 0.f);
            if (BNIN) {
                int k4 = i & 15;
                float4 sc = ((const float4*)scale)[k4];
                float4 sh = ((const float4*)shift)[k4];
                v.x = fmaxf(fmaf(v.x, sc.x, sh.x), 0.f);
                v.y = fmaxf(fmaf(v.y, sc.y, sh.y), 0.f);
                v.z = fmaxf(fmaf(v.z, sc.z, sh.z), 0.f);
                v.w = fmaxf(fmaf(v.w, sc.w, sh.w), 0.f);
            }
            Xsv[i] = v;
        }
    }
    __syncthreads();

    const int tr = tid >> 4, tc = tid & 15;
    const int r0 = tr * 8, c0 = tc * 4;
    float acc[8][4];
#pragma unroll
    for (int i = 0; i < 8; i++)
#pragma unroll
        for (int j = 0; j < 4; j++) acc[i][j] = 0.f;

#pragma unroll 16
    for (int k = 0; k < EMB; k++) {
        float4 b = *(const float4*)(Ws + k * EMB + c0);
#pragma unroll
        for (int i = 0; i < 8; i++) {
            float a = Xs[(r0 + i) * EMB + k];
            acc[i][0] = fmaf(a, b.x, acc[i][0]);
            acc[i][1] = fmaf(a, b.y, acc[i][1]);
            acc[i][2] = fmaf(a, b.z, acc[i][2]);
            acc[i][3] = fmaf(a, b.w, acc[i][3]);
        }
    }

    float4 bi = make_float4(0.f, 0.f, 0.f, 0.f);
    if (BIAS) bi = ((const float4*)bias)[tc];
    float ls[4] = {0.f, 0.f, 0.f, 0.f}, lq[4] = {0.f, 0.f, 0.f, 0.f};
#pragma unroll
    for (int i = 0; i < 8; i++) {
        int r = r0 + i;
        if (r < validRows) {
            float4 o;
            o.x = acc[i][0] + bi.x; o.y = acc[i][1] + bi.y;
            o.z = acc[i][2] + bi.z; o.w = acc[i][3] + bi.w;
            if (OUT32) {
                float4* op = (float4*)(out + (rowbase + r) * EMB + c0);
                if (ACCUM) {
                    float4 pv = *op;
                    o.x += pv.x; o.y += pv.y; o.z += pv.z; o.w += pv.w;
                }
                *op = o;
            }
            if (SHADOW) {
                __half* hp = shadow + (rowbase + r) * EMB + c0;
                *(__half2*)(hp)     = __floats2half2_rn(o.x, o.y);
                *(__half2*)(hp + 2) = __floats2half2_rn(o.z, o.w);
            }
            if (STATS) {
                ls[0] += o.x; lq[0] += o.x * o.x;
                ls[1] += o.y; lq[1] += o.y * o.y;
                ls[2] += o.z; lq[2] += o.z * o.z;
                ls[3] += o.w; lq[3] += o.w * o.w;
            }
        }
    }

    if (STATS) {
        __syncthreads();
        float* red = Xs;
#pragma unroll
        for (int j = 0; j < 4; j++) {
            red[tr * EMB + c0 + j]        = ls[j];
            red[1024 + tr * EMB + c0 + j] = lq[j];
        }
        __syncthreads();
        if (tid < EMB) {
            float s = 0.f, q = 0.f;
#pragma unroll
            for (int t = 0; t < 16; t++) {
                s += red[t * EMB + tid];
                q += red[1024 + t * EMB + tid];
            }
            atomicAdd(stat + tid, s);
            atomicAdd(stat + EMB + tid, q);
        }
    }
}

// ---------------- BN1 stats from fp16 P/Q (no X1 materialization) ----------------
__global__ void __launch_bounds__(256) k_edge_stats1(const void* ei, const float* __restrict__ mb1) {
    const int gid = blockIdx.x * 256 + threadIdx.x;
    const int lane = gid & 15;
    const int c0 = lane * 4;
    const int estride = (EDGE_GRID * 256) >> 4;
    const int is64 = g_is64;
    float4 b = ((const float4*)mb1)[lane];
    float s0 = 0, s1 = 0, s2 = 0, s3 = 0, q0 = 0, q1 = 0, q2 = 0, q3 = 0;
    for (int e = gid >> 4; e < NE; e += estride) {
        int src = ld_idx(ei, e, is64);
        int dst = ld_idx(ei, (long)NE + e, is64);
        uint2 pw = *(const uint2*)(g_P16 + (size_t)dst * EMB + c0);
        uint2 qw = *(const uint2*)(g_Q16 + (size_t)src * EMB + c0);
        float2 p01 = __half22float2(*(__half2*)&pw.x);
        float2 p23 = __half22float2(*(__half2*)&pw.y);
        float2 q01 = __half22float2(*(__half2*)&qw.x);
        float2 q23 = __half22float2(*(__half2*)&qw.y);
        float x0 = p01.x + q01.x + b.x, x1 = p01.y + q01.y + b.y;
        float x2 = p23.x + q23.x + b.z, x3 = p23.y + q23.y + b.w;
        s0 += x0; q0 += x0 * x0;
        s1 += x1; q1 += x1 * x1;
        s2 += x2; q2 += x2 * x2;
        s3 += x3; q3 += x3 * x3;
    }
    __shared__ float red[128];
    if (threadIdx.x < 128) red[threadIdx.x] = 0.f;
    __syncthreads();
    atomicAdd(&red[c0 + 0], s0); atomicAdd(&red[c0 + 1], s1);
    atomicAdd(&red[c0 + 2], s2); atomicAdd(&red[c0 + 3], s3);
    atomicAdd(&red[64 + c0 + 0], q0); atomicAdd(&red[64 + c0 + 1], q1);
    atomicAdd(&red[64 + c0 + 2], q2); atomicAdd(&red[64 + c0 + 3], q3);
    __syncthreads();
    if (threadIdx.x < 128) atomicAdd(&g_stat[threadIdx.x], red[threadIdx.x]);
}

// ---------------- fused edge GEMM via mma.sync tf32, fp16 gather, fp16 X2 out ----------------
// X2[tile] = relu(bn1'(P[dst]+Q[src])) @ mW2 + mb2; BN2 stats computed on the
// fp16-ROUNDED values so bn2 is exactly the BN of the stored X2.
__global__ void __launch_bounds__(256) k_edge_fused(const void* ei, const float* __restrict__ mW2,
                                                    const float* __restrict__ mb2) {
    extern __shared__ char smem[];
    float* As   = (float*)(smem + OFF_AS);      // [128][68]
    float* Bf   = (float*)(smem + OFF_BF);      // [(ks*8+nt)*32 + lane][2]
    int* s_src  = (int*)(smem + OFF_SRC);
    int* s_dst  = (int*)(smem + OFF_DST);
    float* sc_s = (float*)(smem + OFF_SC);
    float* sh_s = (float*)(smem + OFF_SH);
    float* b2_s = (float*)(smem + OFF_B2);
    float* red  = (float*)(smem + OFF_RED);

    const int tid = threadIdx.x;
    const int wid = tid >> 5;
    const int lane = tid & 31;
    const int gidq = lane >> 2;
    const int tig = lane & 3;
    const int is64 = g_is64;

    for (int i = tid; i < 2048; i += 256) {
        int slab = i >> 5, ln = i & 31;
        int ks = slab >> 3, nt = slab & 7;
        int g = ln >> 2, t = ln & 3;
        uint32_t b0 = f2tf32(mW2[(ks * 8 + t) * 64 + nt * 8 + g]);
        uint32_t b1 = f2tf32(mW2[(ks * 8 + t + 4) * 64 + nt * 8 + g]);
        ((uint32_t*)Bf)[2 * i]     = b0;
        ((uint32_t*)Bf)[2 * i + 1] = b1;
    }
    if (tid < EMB) {
        sc_s[tid] = g_bn[tid];
        sh_s[tid] = g_bn[EMB + tid];
        b2_s[tid] = mb2[tid];
    }
    if (tid < 128) red[tid] = 0.f;
    __syncthreads();

    float st_s[16], st_q[16];
#pragma unroll
    for (int i = 0; i < 16; i++) { st_s[i] = 0.f; st_q[i] = 0.f; }

    for (int tile = blockIdx.x; tile < NTILES; tile += gridDim.x) {
        if (tid < 128) {
            s_src[tid] = ld_idx(ei, (long)tile * 128 + tid, is64);
            s_dst[tid] = ld_idx(ei, (long)NE + (long)tile * 128 + tid, is64);
        }
        __syncthreads();

        // gather fp16 P,Q + bn1' + relu + tf32-cvt -> As[row][c] (row stride 68)
        {
            const int row = tid >> 1, half = tid & 1;
            const uint4* Pp = (const uint4*)(g_P16 + (size_t)s_dst[row] * EMB) + half * 4;
            const uint4* Qp = (const uint4*)(g_Q16 + (size_t)s_src[row] * EMB) + half * 4;
            uint32_t* dstw = (uint32_t*)(As + row * 68 + half * 32);
#pragma unroll
            for (int f2 = 0; f2 < 4; f2++) {
                uint4 pw = Pp[f2], qw = Qp[f2];
                int cg = half * 32 + f2 * 8;
                float4 sc0 = *(const float4*)(sc_s + cg);
                float4 sh0 = *(const float4*)(sh_s + cg);
                float4 sc1 = *(const float4*)(sc_s + cg + 4);
                float4 sh1 = *(const float4*)(sh_s + cg + 4);
                float2 p01 = __half22float2(*(__half2*)&pw.x);
                float2 p23 = __half22float2(*(__half2*)&pw.y);
                float2 p45 = __half22float2(*(__half2*)&pw.z);
                float2 p67 = __half22float2(*(__half2*)&pw.w);
                float2 q01 = __half22float2(*(__half2*)&qw.x);
                float2 q23 = __half22float2(*(__half2*)&qw.y);
                float2 q45 = __half22float2(*(__half2*)&qw.z);
                float2 q67 = __half22float2(*(__half2*)&qw.w);
                uint4 o1, o2;
                o1.x = f2tf32(fmaxf(fmaf(p01.x + q01.x, sc0.x, sh0.x), 0.f));
                o1.y = f2tf32(fmaxf(fmaf(p01.y + q01.y, sc0.y, sh0.y), 0.f));
                o1.z = f2tf32(fmaxf(fmaf(p23.x + q23.x, sc0.z, sh0.z), 0.f));
                o1.w = f2tf32(fmaxf(fmaf(p23.y + q23.y, sc0.w, sh0.w), 0.f));
                o2.x = f2tf32(fmaxf(fmaf(p45.x + q45.x, sc1.x, sh1.x), 0.f));
                o2.y = f2tf32(fmaxf(fmaf(p45.y + q45.y, sc1.y, sh1.y), 0.f));
                o2.z = f2tf32(fmaxf(fmaf(p67.x + q67.x, sc1.z, sh1.z), 0.f));
                o2.w = f2tf32(fmaxf(fmaf(p67.y + q67.y, sc1.w, sh1.w), 0.f));
                *(uint4*)(dstw + f2 * 8)     = o1;
                *(uint4*)(dstw + f2 * 8 + 4) = o2;
            }
        }
        __syncthreads();

        uint32_t a[8][4];
        {
            const uint32_t* Ab = (const uint32_t*)As + (wid * 16 + gidq) * 68 + tig;
#pragma unroll
            for (int ks = 0; ks < 8; ks++) {
                a[ks][0] = Ab[ks * 8];
                a[ks][1] = Ab[ks * 8 + 8 * 68];
                a[ks][2] = Ab[ks * 8 + 4];
                a[ks][3] = Ab[ks * 8 + 8 * 68 + 4];
            }
        }

        const int row0 = tile * 128 + wid * 16 + gidq;
#pragma unroll
        for (int nt = 0; nt < 8; nt++) {
            float c[4] = {0.f, 0.f, 0.f, 0.f};
#pragma unroll
            for (int ks = 0; ks < 8; ks++) {
                uint2 b = *(const uint2*)((const uint32_t*)Bf + ((ks * 8 + nt) * 32 + lane) * 2);
                mma_tf32(c, a[ks], b.x, b.y);
            }
            int col = nt * 8 + tig * 2;
            float b0 = b2_s[col], b1 = b2_s[col + 1];
            // round to fp16, store, and take stats on the ROUNDED values
            __half2 h01 = __floats2half2_rn(c[0] + b0, c[1] + b1);   // row0
            __half2 h23 = __floats2half2_rn(c[2] + b0, c[3] + b1);   // row0+8
            *(__half2*)(g_X2h + (size_t)row0 * EMB + col)       = h01;
            *(__half2*)(g_X2h + (size_t)(row0 + 8) * EMB + col) = h23;
            float2 r01 = __half22float2(h01);
            float2 r23 = __half22float2(h23);
            st_s[nt * 2]     += r01.x + r23.x;
            st_s[nt * 2 + 1] += r01.y + r23.y;
            st_q[nt * 2]     += r01.x * r01.x + r23.x * r23.x;
            st_q[nt * 2 + 1] += r01.y * r01.y + r23.y * r23.y;
        }
        __syncthreads();
    }

#pragma unroll
    for (int nt = 0; nt < 8; nt++) {
        int col = nt * 8 + tig * 2;
        atomicAdd(&red[col],          st_s[nt * 2]);
        atomicAdd(&red[col + 1],      st_s[nt * 2 + 1]);
        atomicAdd(&red[64 + col],     st_q[nt * 2]);
        atomicAdd(&red[64 + col + 1], st_q[nt * 2 + 1]);
    }
    __syncthreads();
    if (tid < 128) atomicAdd(&g_stat[128 + tid], red[tid]);
}

// ---------------- edge scatter: aggr[dst] += relu(bn2(X2[e])), fp16 reads, red.v4 ----------------
__global__ void __launch_bounds__(256) k_edge_scatter(const void* ei) {
    const int gid = blockIdx.x * 256 + threadIdx.x;
    const int lane = gid & 15;
    const int c0 = lane * 4;
    const int estride = (EDGE_GRID * 256) >> 4;
    const int is64 = g_is64;
    float4 sc = *(const float4*)(g_bn + 128 + c0);
    float4 sh = *(const float4*)(g_bn + 128 + 64 + c0);
#pragma unroll 2
    for (int e = gid >> 4; e < NE; e += estride) {
        int dst = ld_idx(ei, (long)NE + e, is64);
        uint2 xw = *(const uint2*)(g_X2h + (size_t)e * EMB + c0);
        float2 x01 = __half22float2(*(__half2*)&xw.x);
        float2 x23 = __half22float2(*(__half2*)&xw.y);
        float y0 = fmaxf(fmaf(x01.x, sc.x, sh.x), 0.f);
        float y1 = fmaxf(fmaf(x01.y, sc.y, sh.y), 0.f);
        float y2 = fmaxf(fmaf(x23.x, sc.z, sh.z), 0.f);
        float y3 = fmaxf(fmaf(x23.y, sc.w, sh.w), 0.f);
        float* a = g_aggr + (size_t)dst * EMB + c0;
        asm volatile("red.global.add.v4.f32 [%0], {%1, %2, %3, %4};"
                     :: "l"(a), "f"(y0), "f"(y1), "f"(y2), "f"(y3) : "memory");
    }
}

// ---------------- BN finalize ----------------
__global__ void k_finalize(int stage, float invcnt,
                           const float* __restrict__ gamma, const float* __restrict__ beta,
                           const float* __restrict__ bias) {
    int c = threadIdx.x;
    if (c >= EMB) return;
    float mu = g_stat[stage * 128 + c] * invcnt;
    float var = g_stat[stage * 128 + EMB + c] * invcnt - mu * mu;
    float sc = gamma[c] * rsqrtf(var + EPS);
    float sh = beta[c] - mu * sc;
    if (bias) sh += bias[c] * sc;   // fold linear bias into shift
    g_bn[stage * 128 + c] = sc;
    g_bn[stage * 128 + EMB + c] = sh;
}

// ---------------- final prediction ----------------
__global__ void __launch_bounds__(256) k_pred(const float* __restrict__ Wp,
                                              const float* __restrict__ bp,
                                              float* __restrict__ out) {
    int n = blockIdx.x * blockDim.x + threadIdx.x;
    if (n >= NN) return;
    float acc = bp[0];
    const float4* u = (const float4*)(g_Q + (size_t)n * EMB);
#pragma unroll
    for (int c4 = 0; c4 < 16; c4++) {
        float4 v  = u[c4];
        float4 sc = ((const float4*)(g_bn + 3 * 128))[c4];
        float4 sh = ((const float4*)(g_bn + 3 * 128 + 64))[c4];
        float4 w  = ((const float4*)Wp)[c4];
        acc = fmaf(fmaxf(fmaf(v.x, sc.x, sh.x), 0.f), w.x, acc);
        acc = fmaf(fmaxf(fmaf(v.y, sc.y, sh.y), 0.f), w.y, acc);
        acc = fmaf(fmaxf(fmaf(v.z, sc.z, sh.z), 0.f), w.z, acc);
        acc = fmaf(fmaxf(fmaf(v.w, sc.w, sh.w), 0.f), w.w, acc);
    }
    out[n] = acc;
}

// ---------------- launch ----------------
extern "C" void kernel_launch(void* const* d_in, const int* in_sizes, int n_in,
                              void* d_out, int out_size) {
    const float* pos = (const float*)d_in[0];
    const float* vel = (const float*)d_in[1];
    const void*  ei  = d_in[2];
    const float* Win = (const float*)d_in[3];
    const float* bin = (const float*)d_in[4];
    const float* mW1 = (const float*)d_in[5];
    const float* mb1 = (const float*)d_in[6];
    const float* mg1 = (const float*)d_in[7];
    const float* mB1 = (const float*)d_in[8];
    const float* mW2 = (const float*)d_in[9];
    const float* mb2 = (const float*)d_in[10];
    const float* mg2 = (const float*)d_in[11];
    const float* mB2 = (const float*)d_in[12];
    const float* uW1 = (const float*)d_in[13];
    const float* ub1 = (const float*)d_in[14];
    const float* ug1 = (const float*)d_in[15];
    const float* uB1 = (const float*)d_in[16];
    const float* uW2 = (const float*)d_in[17];
    const float* ub2 = (const float*)d_in[18];
    const float* ug2 = (const float*)d_in[19];
    const float* uB2 = (const float*)d_in[20];
    const float* Wp  = (const float*)d_in[21];
    const float* bp  = (const float*)d_in[22];
    float* out = (float*)d_out;

    static bool attr_set = false;
    if (!attr_set) {
        cudaFuncSetAttribute(k_edge_fused, cudaFuncAttributeMaxDynamicSharedMemorySize, SMEM_FUSED);
        attr_set = true;
    }

    float *pH, *pP, *pQ, *pAg, *pStat, *pBn;
    __half *pP16, *pQ16;
    cudaGetSymbolAddress((void**)&pH, g_h);
    cudaGetSymbolAddress((void**)&pP, g_P);
    cudaGetSymbolAddress((void**)&pQ, g_Q);
    cudaGetSymbolAddress((void**)&pP16, g_P16);
    cudaGetSymbolAddress((void**)&pQ16, g_Q16);
    cudaGetSymbolAddress((void**)&pAg, g_aggr);
    cudaGetSymbolAddress((void**)&pStat, g_stat);
    cudaGetSymbolAddress((void**)&pBn, g_bn);

    cudaMemsetAsync(pAg, 0, (size_t)NN * EMB * sizeof(float));
    cudaMemsetAsync(pStat, 0, 4 * 2 * EMB * sizeof(float));

    const int GN = (NN + 127) / 128;

    k_detect<<<1, 256>>>((const unsigned int*)ei);
    k_node_embed<<<(NN + 255) / 256, 256>>>(pos, vel, Win, bin);

    // P16 = h @ mW1_top ; Q16 = h @ mW1_bot  (fp16 only — sole edge-phase inputs)
    k_gemm64<false, false, false, false, true, false><<<GN, 256>>>(pH, mW1, nullptr, nullptr, nullptr, nullptr, pP16, nullptr, NN);
    k_gemm64<false, false, false, false, true, false><<<GN, 256>>>(pH, mW1 + 64 * 64, nullptr, nullptr, nullptr, nullptr, pQ16, nullptr, NN);

    // BN1 stats from fp16 P/Q, finalize with mb1 folded into shift
    k_edge_stats1<<<EDGE_GRID, 256>>>(ei, mb1);
    k_finalize<<<1, 64>>>(0, 1.0f / (float)NE, mg1, mB1, mb1);

    // fused: X2(fp16) = relu(bn1'(P16[dst]+Q16[src])) @ mW2 + mb2 (mma.sync tf32) + BN2 stats
    k_edge_fused<<<FUSED_GRID, 256, SMEM_FUSED>>>(ei, mW2, mb2);
    k_finalize<<<1, 64>>>(1, 1.0f / (float)NE, mg2, mB2, nullptr);

    // aggr = segment_sum(relu(bn2(X2)), dst)
    k_edge_scatter<<<EDGE_GRID, 256>>>(ei);

    // update MLP layer 1: T1 = h @ uW1_top + aggr @ uW1_bot + ub1, BN3 stats
    k_gemm64<false, false, false, false, false, true><<<GN, 256>>>(pH, uW1, nullptr, nullptr, nullptr, pP, nullptr, nullptr, NN);
    k_gemm64<false, true, true, true, false, true><<<GN, 256>>>(pAg, uW1 + 64 * 64, ub1, nullptr, nullptr, pP, nullptr, pStat + 256, NN);
    k_finalize<<<1, 64>>>(2, 1.0f / (float)NN, ug1, uB1, nullptr);

    // update MLP layer 2: U2 = relu(bn3(T1)) @ uW2 + ub2, BN4 stats
    k_gemm64<true, false, true, true, false, true><<<GN, 256>>>(pP, uW2, ub2, pBn + 256, pBn + 256 + 64, pQ, nullptr, pStat + 384, NN);
    k_finalize<<<1, 64>>>(3, 1.0f / (float)NN, ug2, uB2, nullptr);

    // out = relu(bn4(U2)) @ W_pred + b_pred
    k_pred<<<(NN + 255) / 256, 256>>>(Wp, bp, out);
}

// round 15
// speedup vs baseline: 1.5286x; 1.1075x over previous
#include <cuda_runtime.h>
#include <cuda_fp16.h>
#include <cstdint>

#define NN 100000
#define NE 1600000
#define EMB 64
#define EPS 1e-5f
#define EDGE_GRID 2048
#define NTILES (NE / 128)
#define FUSED_GRID 444

// dynamic smem layout for fused kernel (bytes)
#define OFF_AS    0        // As[128 rows][72 halves] fp16, 144B row stride  = 18432
#define OFF_BF    18432    // B frag-major [32 slabs][32 lanes][uint2]       = 8192
#define OFF_SC    26624    // bn1 scale (64 f32)
#define OFF_SH    26880    // bn1 shift' (64 f32, includes mb1)
#define OFF_B2    27136    // mb2 (64 f32)
#define OFF_RED   27392    // stats reduction 128 f32
#define SMEM_FUSED 27904

// ---------------- scratch (device globals: allocation-free contract) ----------------
__device__ __align__(256) float g_h[NN * EMB];
__device__ __align__(256) float g_P[NN * EMB];     // reused as T1 (upd layer-1 out)
__device__ __align__(256) float g_Q[NN * EMB];     // reused as U2 (upd layer-2 out)
__device__ __align__(256) __half g_P16[NN * EMB];  // fp16 P/Q: sole edge-phase inputs
__device__ __align__(256) __half g_Q16[NN * EMB];
__device__ __align__(256) float g_aggr[NN * EMB];
__device__ __align__(256) __half g_X2h[(size_t)NE * EMB];   // fp16 X2
__device__ float g_stat[4 * 2 * EMB];   // per BN stage: [sum(64) | sumsq(64)]
__device__ float g_bn[4 * 2 * EMB];     // per BN stage: [scale(64) | shift(64)]
__device__ int   g_is64;

// ---------------- helpers ----------------
__device__ __forceinline__ uint32_t smem_u32(const void* p) {
    uint32_t a;
    asm("{ .reg .u64 t; cvta.to.shared.u64 t, %1; cvt.u32.u64 %0, t; }" : "=r"(a) : "l"(p));
    return a;
}
__device__ __forceinline__ void ldmatrix_x4(uint32_t& a0, uint32_t& a1, uint32_t& a2, uint32_t& a3,
                                            uint32_t addr) {
    asm volatile("ldmatrix.sync.aligned.m8n8.x4.shared.b16 {%0,%1,%2,%3}, [%4];"
                 : "=r"(a0), "=r"(a1), "=r"(a2), "=r"(a3) : "r"(addr));
}
__device__ __forceinline__ void mma_f16(float* c, const uint32_t* a, uint32_t b0, uint32_t b1) {
    asm volatile(
        "mma.sync.aligned.m16n8k16.row.col.f32.f16.f16.f32 "
        "{%0,%1,%2,%3}, {%4,%5,%6,%7}, {%8,%9}, {%0,%1,%2,%3};"
        : "+f"(c[0]), "+f"(c[1]), "+f"(c[2]), "+f"(c[3])
        : "r"(a[0]), "r"(a[1]), "r"(a[2]), "r"(a[3]), "r"(b0), "r"(b1));
}

// ---------------- int32/int64 edge-index detection ----------------
__global__ void k_detect(const unsigned int* ei_words) {
    __shared__ int any;
    if (threadIdx.x == 0) any = 0;
    __syncthreads();
    for (int i = threadIdx.x; i < 2048; i += blockDim.x)
        if (ei_words[2 * i + 1] != 0u) atomicOr(&any, 1);
    __syncthreads();
    if (threadIdx.x == 0) g_is64 = any ? 0 : 1;
}
__device__ __forceinline__ int ld_idx(const void* ei, long i, int is64) {
    if (is64) return (int)((const long long*)ei)[i];
    return ((const int*)ei)[i];
}

// ---------------- node embedding ----------------
__global__ void __launch_bounds__(256) k_node_embed(
    const float* __restrict__ pos, const float* __restrict__ vel,
    const float* __restrict__ Win, const float* __restrict__ bin)
{
    int n = blockIdx.x * blockDim.x + threadIdx.x;
    if (n >= NN) return;
    float p0 = pos[2 * n], p1 = pos[2 * n + 1];
    float v0 = vel[2 * n], v1 = vel[2 * n + 1];
    float4* out = (float4*)(g_h + (size_t)n * EMB);
#pragma unroll
    for (int c4 = 0; c4 < 16; c4++) {
        float4 w0 = ((const float4*)(Win + 0 * EMB))[c4];
        float4 w1 = ((const float4*)(Win + 1 * EMB))[c4];
        float4 w2 = ((const float4*)(Win + 2 * EMB))[c4];
        float4 w3 = ((const float4*)(Win + 3 * EMB))[c4];
        float4 b  = ((const float4*)bin)[c4];
        float4 o;
        o.x = fmaf(p0, w0.x, fmaf(p1, w1.x, fmaf(v0, w2.x, fmaf(v1, w3.x, b.x))));
        o.y = fmaf(p0, w0.y, fmaf(p1, w1.y, fmaf(v0, w2.y, fmaf(v1, w3.y, b.y))));
        o.z = fmaf(p0, w0.z, fmaf(p1, w1.z, fmaf(v0, w2.z, fmaf(v1, w3.z, b.z))));
        o.w = fmaf(p0, w0.w, fmaf(p1, w1.w, fmaf(v0, w2.w, fmaf(v1, w3.w, b.w))));
        out[c4] = o;
    }
}

// ---------------- generic rows x 64 @ 64 x 64 GEMM with fused epilogues ----------------
template <bool BNIN, bool ACCUM, bool BIAS, bool STATS, bool SHADOW, bool OUT32>
__global__ void __launch_bounds__(256) k_gemm64(
    const float* __restrict__ X, const float* __restrict__ W,
    const float* __restrict__ bias, const float* __restrict__ scale,
    const float* __restrict__ shift, float* __restrict__ out,
    __half* __restrict__ shadow, float* __restrict__ stat, int rows)
{
    __shared__ float Xs[128 * EMB];
    __shared__ float Ws[EMB * EMB];
    const int tid = threadIdx.x;
    const long rowbase = (long)blockIdx.x * 128;
    long vr = (long)rows - rowbase;
    const int validRows = (vr > 128) ? 128 : (int)vr;

    {
        const float4* Wg = (const float4*)W;
        float4* Wsv = (float4*)Ws;
        for (int i = tid; i < 1024; i += 256) Wsv[i] = Wg[i];
    }
    {
        const float4* Xg = (const float4*)(X + rowbase * EMB);
        float4* Xsv = (float4*)Xs;
        for (int i = tid; i < 2048; i += 256) {
            int r = i >> 4;
            float4 v;
            if (r < validRows) v = Xg[i];
            else v = make_float4(0.f, 0.f, 0.f, 0.f);
            if (BNIN) {
                int k4 = i & 15;
                float4 sc = ((const float4*)scale)[k4];
                float4 sh = ((const float4*)shift)[k4];
                v.x = fmaxf(fmaf(v.x, sc.x, sh.x), 0.f);
                v.y = fmaxf(fmaf(v.y, sc.y, sh.y), 0.f);
                v.z = fmaxf(fmaf(v.z, sc.z, sh.z), 0.f);
                v.w = fmaxf(fmaf(v.w, sc.w, sh.w), 0.f);
            }
            Xsv[i] = v;
        }
    }
    __syncthreads();

    const int tr = tid >> 4, tc = tid & 15;
    const int r0 = tr * 8, c0 = tc * 4;
    float acc[8][4];
#pragma unroll
    for (int i = 0; i < 8; i++)
#pragma unroll
        for (int j = 0; j < 4; j++) acc[i][j] = 0.f;

#pragma unroll 16
    for (int k = 0; k < EMB; k++) {
        float4 b = *(const float4*)(Ws + k * EMB + c0);
#pragma unroll
        for (int i = 0; i < 8; i++) {
            float a = Xs[(r0 + i) * EMB + k];
            acc[i][0] = fmaf(a, b.x, acc[i][0]);
            acc[i][1] = fmaf(a, b.y, acc[i][1]);
            acc[i][2] = fmaf(a, b.z, acc[i][2]);
            acc[i][3] = fmaf(a, b.w, acc[i][3]);
        }
    }

    float4 bi = make_float4(0.f, 0.f, 0.f, 0.f);
    if (BIAS) bi = ((const float4*)bias)[tc];
    float ls[4] = {0.f, 0.f, 0.f, 0.f}, lq[4] = {0.f, 0.f, 0.f, 0.f};
#pragma unroll
    for (int i = 0; i < 8; i++) {
        int r = r0 + i;
        if (r < validRows) {
            float4 o;
            o.x = acc[i][0] + bi.x; o.y = acc[i][1] + bi.y;
            o.z = acc[i][2] + bi.z; o.w = acc[i][3] + bi.w;
            if (OUT32) {
                float4* op = (float4*)(out + (rowbase + r) * EMB + c0);
                if (ACCUM) {
                    float4 pv = *op;
                    o.x += pv.x; o.y += pv.y; o.z += pv.z; o.w += pv.w;
                }
                *op = o;
            }
            if (SHADOW) {
                __half* hp = shadow + (rowbase + r) * EMB + c0;
                *(__half2*)(hp)     = __floats2half2_rn(o.x, o.y);
                *(__half2*)(hp + 2) = __floats2half2_rn(o.z, o.w);
            }
            if (STATS) {
                ls[0] += o.x; lq[0] += o.x * o.x;
                ls[1] += o.y; lq[1] += o.y * o.y;
                ls[2] += o.z; lq[2] += o.z * o.z;
                ls[3] += o.w; lq[3] += o.w * o.w;
            }
        }
    }

    if (STATS) {
        __syncthreads();
        float* red = Xs;
#pragma unroll
        for (int j = 0; j < 4; j++) {
            red[tr * EMB + c0 + j]        = ls[j];
            red[1024 + tr * EMB + c0 + j] = lq[j];
        }
        __syncthreads();
        if (tid < EMB) {
            float s = 0.f, q = 0.f;
#pragma unroll
            for (int t = 0; t < 16; t++) {
                s += red[t * EMB + tid];
                q += red[1024 + t * EMB + tid];
            }
            atomicAdd(stat + tid, s);
            atomicAdd(stat + EMB + tid, q);
        }
    }
}

// ---------------- BN1 stats from fp16 P/Q (no X1 materialization) ----------------
__global__ void __launch_bounds__(256) k_edge_stats1(const void* ei, const float* __restrict__ mb1) {
    const int gid = blockIdx.x * 256 + threadIdx.x;
    const int lane = gid & 15;
    const int c0 = lane * 4;
    const int estride = (EDGE_GRID * 256) >> 4;
    const int is64 = g_is64;
    float4 b = ((const float4*)mb1)[lane];
    float s0 = 0, s1 = 0, s2 = 0, s3 = 0, q0 = 0, q1 = 0, q2 = 0, q3 = 0;
    for (int e = gid >> 4; e < NE; e += estride) {
        int src = ld_idx(ei, e, is64);
        int dst = ld_idx(ei, (long)NE + e, is64);
        uint2 pw = *(const uint2*)(g_P16 + (size_t)dst * EMB + c0);
        uint2 qw = *(const uint2*)(g_Q16 + (size_t)src * EMB + c0);
        float2 p01 = __half22float2(*(__half2*)&pw.x);
        float2 p23 = __half22float2(*(__half2*)&pw.y);
        float2 q01 = __half22float2(*(__half2*)&qw.x);
        float2 q23 = __half22float2(*(__half2*)&qw.y);
        float x0 = p01.x + q01.x + b.x, x1 = p01.y + q01.y + b.y;
        float x2 = p23.x + q23.x + b.z, x3 = p23.y + q23.y + b.w;
        s0 += x0; q0 += x0 * x0;
        s1 += x1; q1 += x1 * x1;
        s2 += x2; q2 += x2 * x2;
        s3 += x3; q3 += x3 * x3;
    }
    __shared__ float red[128];
    if (threadIdx.x < 128) red[threadIdx.x] = 0.f;
    __syncthreads();
    atomicAdd(&red[c0 + 0], s0); atomicAdd(&red[c0 + 1], s1);
    atomicAdd(&red[c0 + 2], s2); atomicAdd(&red[c0 + 3], s3);
    atomicAdd(&red[64 + c0 + 0], q0); atomicAdd(&red[64 + c0 + 1], q1);
    atomicAdd(&red[64 + c0 + 2], q2); atomicAdd(&red[64 + c0 + 3], q3);
    __syncthreads();
    if (threadIdx.x < 128) atomicAdd(&g_stat[threadIdx.x], red[threadIdx.x]);
}

// ---------------- fused edge GEMM via mma.sync fp16 (m16n8k16), fp16 gather + fp16 X2 ----------------
// X2[tile] = relu(bn1'(P[dst]+Q[src])) @ mW2 + mb2; BN2 stats on fp16-rounded values.
// As: fp16 [128 rows][72 halves] (144B stride, conflict-free for ldmatrix).
// Bf: frag-major fp16 pairs, 32 slabs (ks 0..3 x nt 0..7) x 32 lanes x uint2.
__global__ void __launch_bounds__(256) k_edge_fused(const void* ei, const float* __restrict__ mW2,
                                                    const float* __restrict__ mb2) {
    extern __shared__ char smem[];
    __half* As  = (__half*)(smem + OFF_AS);
    uint2* Bf   = (uint2*)(smem + OFF_BF);
    float* sc_s = (float*)(smem + OFF_SC);
    float* sh_s = (float*)(smem + OFF_SH);
    float* b2_s = (float*)(smem + OFF_B2);
    float* red  = (float*)(smem + OFF_RED);

    const uint32_t As_u32 = smem_u32(As);
    const int tid = threadIdx.x;
    const int wid = tid >> 5;
    const int lane = tid & 31;
    const int gidq = lane >> 2;    // 0..7
    const int tig = lane & 3;      // 0..3
    const int is64 = g_is64;

    // stage B fragments (fp16, m16n8k16 layout): slab = ks*8+nt
    // b0 = {W[ks*16+2t][col], W[ks*16+2t+1][col]}, b1 = same +8 k-rows; col = nt*8+g
    for (int i = tid; i < 1024; i += 256) {
        int slab = i >> 5, ln = i & 31;
        int ks = slab >> 3, nt = slab & 7;
        int g = ln >> 2, t = ln & 3;
        int col = nt * 8 + g;
        int k0 = ks * 16 + 2 * t;
        __half2 b0 = __floats2half2_rn(mW2[k0 * 64 + col],       mW2[(k0 + 1) * 64 + col]);
        __half2 b1 = __floats2half2_rn(mW2[(k0 + 8) * 64 + col], mW2[(k0 + 9) * 64 + col]);
        uint2 bb;
        bb.x = *(uint32_t*)&b0;
        bb.y = *(uint32_t*)&b1;
        Bf[i] = bb;
    }
    if (tid < EMB) {
        sc_s[tid] = g_bn[tid];
        sh_s[tid] = g_bn[EMB + tid];
        b2_s[tid] = mb2[tid];
    }
    if (tid < 128) red[tid] = 0.f;
    __syncthreads();

    float st_s[16], st_q[16];
#pragma unroll
    for (int i = 0; i < 16; i++) { st_s[i] = 0.f; st_q[i] = 0.f; }

    // ldmatrix address (constant per thread, per-ks offset added in loop):
    // matrix m = lane>>3, r = lane&7; row = wid*16 + (m&1)*8 + r; byte = row*144 + (m>>1)*16
    const int lm_m = lane >> 3, lm_r = lane & 7;
    const uint32_t lm_base = As_u32 + (uint32_t)((wid * 16 + (lm_m & 1) * 8 + lm_r) * 144 + (lm_m >> 1) * 16);

    for (int tile = blockIdx.x; tile < NTILES; tile += gridDim.x) {
        // gather fp16 P,Q + bn1' + relu -> As fp16 (direct per-thread index loads)
        {
            const int row = tid >> 1, half = tid & 1;
            long ebase = (long)tile * 128 + row;
            int src = ld_idx(ei, ebase, is64);
            int dst = ld_idx(ei, (long)NE + ebase, is64);
            const uint4* Pp = (const uint4*)(g_P16 + (size_t)dst * EMB) + half * 4;
            const uint4* Qp = (const uint4*)(g_Q16 + (size_t)src * EMB) + half * 4;
            uint4* dstw = (uint4*)((char*)As + row * 144 + half * 64);
#pragma unroll
            for (int f2 = 0; f2 < 4; f2++) {
                uint4 pw = Pp[f2], qw = Qp[f2];
                int cg = half * 32 + f2 * 8;
                float4 sc0 = *(const float4*)(sc_s + cg);
                float4 sh0 = *(const float4*)(sh_s + cg);
                float4 sc1 = *(const float4*)(sc_s + cg + 4);
                float4 sh1 = *(const float4*)(sh_s + cg + 4);
                float2 p01 = __half22float2(*(__half2*)&pw.x);
                float2 p23 = __half22float2(*(__half2*)&pw.y);
                float2 p45 = __half22float2(*(__half2*)&pw.z);
                float2 p67 = __half22float2(*(__half2*)&pw.w);
                float2 q01 = __half22float2(*(__half2*)&qw.x);
                float2 q23 = __half22float2(*(__half2*)&qw.y);
                float2 q45 = __half22float2(*(__half2*)&qw.z);
                float2 q67 = __half22float2(*(__half2*)&qw.w);
                __half2 h0 = __floats2half2_rn(fmaxf(fmaf(p01.x + q01.x, sc0.x, sh0.x), 0.f),
                                               fmaxf(fmaf(p01.y + q01.y, sc0.y, sh0.y), 0.f));
                __half2 h1 = __floats2half2_rn(fmaxf(fmaf(p23.x + q23.x, sc0.z, sh0.z), 0.f),
                                               fmaxf(fmaf(p23.y + q23.y, sc0.w, sh0.w), 0.f));
                __half2 h2 = __floats2half2_rn(fmaxf(fmaf(p45.x + q45.x, sc1.x, sh1.x), 0.f),
                                               fmaxf(fmaf(p45.y + q45.y, sc1.y, sh1.y), 0.f));
                __half2 h3 = __floats2half2_rn(fmaxf(fmaf(p67.x + q67.x, sc1.z, sh1.z), 0.f),
                                               fmaxf(fmaf(p67.y + q67.y, sc1.w, sh1.w), 0.f));
                uint4 o;
                o.x = *(uint32_t*)&h0; o.y = *(uint32_t*)&h1;
                o.z = *(uint32_t*)&h2; o.w = *(uint32_t*)&h3;
                dstw[f2] = o;
            }
        }
        __syncthreads();

        // A fragments via ldmatrix: a[ks][4], ks = 0..3 (k-offset = ks*32 bytes)
        uint32_t a[4][4];
#pragma unroll
        for (int ks = 0; ks < 4; ks++)
            ldmatrix_x4(a[ks][0], a[ks][1], a[ks][2], a[ks][3], lm_base + ks * 32);

        const int row0 = tile * 128 + wid * 16 + gidq;
#pragma unroll
        for (int nt = 0; nt < 8; nt++) {
            float c[4] = {0.f, 0.f, 0.f, 0.f};
#pragma unroll
            for (int ks = 0; ks < 4; ks++) {
                uint2 b = Bf[(ks * 8 + nt) * 32 + lane];
                mma_f16(c, a[ks], b.x, b.y);
            }
            int col = nt * 8 + tig * 2;
            float b0 = b2_s[col], b1 = b2_s[col + 1];
            __half2 h01 = __floats2half2_rn(c[0] + b0, c[1] + b1);   // row0
            __half2 h23 = __floats2half2_rn(c[2] + b0, c[3] + b1);   // row0+8
            *(__half2*)(g_X2h + (size_t)row0 * EMB + col)       = h01;
            *(__half2*)(g_X2h + (size_t)(row0 + 8) * EMB + col) = h23;
            float2 r01 = __half22float2(h01);
            float2 r23 = __half22float2(h23);
            st_s[nt * 2]     += r01.x + r23.x;
            st_s[nt * 2 + 1] += r01.y + r23.y;
            st_q[nt * 2]     += r01.x * r01.x + r23.x * r23.x;
            st_q[nt * 2 + 1] += r01.y * r01.y + r23.y * r23.y;
        }
        __syncthreads();
    }

#pragma unroll
    for (int nt = 0; nt < 8; nt++) {
        int col = nt * 8 + tig * 2;
        atomicAdd(&red[col],          st_s[nt * 2]);
        atomicAdd(&red[col + 1],      st_s[nt * 2 + 1]);
        atomicAdd(&red[64 + col],     st_q[nt * 2]);
        atomicAdd(&red[64 + col + 1], st_q[nt * 2 + 1]);
    }
    __syncthreads();
    if (tid < 128) atomicAdd(&g_stat[128 + tid], red[tid]);
}

// ---------------- edge scatter: aggr[dst] += relu(bn2(X2[e])), fp16 reads, red.v4 ----------------
__global__ void __launch_bounds__(256) k_edge_scatter(const void* ei) {
    const int gid = blockIdx.x * 256 + threadIdx.x;
    const int lane = gid & 15;
    const int c0 = lane * 4;
    const int estride = (EDGE_GRID * 256) >> 4;
    const int is64 = g_is64;
    float4 sc = *(const float4*)(g_bn + 128 + c0);
    float4 sh = *(const float4*)(g_bn + 128 + 64 + c0);
#pragma unroll 2
    for (int e = gid >> 4; e < NE; e += estride) {
        int dst = ld_idx(ei, (long)NE + e, is64);
        uint2 xw = *(const uint2*)(g_X2h + (size_t)e * EMB + c0);
        float2 x01 = __half22float2(*(__half2*)&xw.x);
        float2 x23 = __half22float2(*(__half2*)&xw.y);
        float y0 = fmaxf(fmaf(x01.x, sc.x, sh.x), 0.f);
        float y1 = fmaxf(fmaf(x01.y, sc.y, sh.y), 0.f);
        float y2 = fmaxf(fmaf(x23.x, sc.z, sh.z), 0.f);
        float y3 = fmaxf(fmaf(x23.y, sc.w, sh.w), 0.f);
        float* a = g_aggr + (size_t)dst * EMB + c0;
        asm volatile("red.global.add.v4.f32 [%0], {%1, %2, %3, %4};"
                     :: "l"(a), "f"(y0), "f"(y1), "f"(y2), "f"(y3) : "memory");
    }
}

// ---------------- BN finalize ----------------
__global__ void k_finalize(int stage, float invcnt,
                           const float* __restrict__ gamma, const float* __restrict__ beta,
                           const float* __restrict__ bias) {
    int c = threadIdx.x;
    if (c >= EMB) return;
    float mu = g_stat[stage * 128 + c] * invcnt;
    float var = g_stat[stage * 128 + EMB + c] * invcnt - mu * mu;
    float sc = gamma[c] * rsqrtf(var + EPS);
    float sh = beta[c] - mu * sc;
    if (bias) sh += bias[c] * sc;   // fold linear bias into shift
    g_bn[stage * 128 + c] = sc;
    g_bn[stage * 128 + EMB + c] = sh;
}

// ---------------- final prediction ----------------
__global__ void __launch_bounds__(256) k_pred(const float* __restrict__ Wp,
                                              const float* __restrict__ bp,
                                              float* __restrict__ out) {
    int n = blockIdx.x * blockDim.x + threadIdx.x;
    if (n >= NN) return;
    float acc = bp[0];
    const float4* u = (const float4*)(g_Q + (size_t)n * EMB);
#pragma unroll
    for (int c4 = 0; c4 < 16; c4++) {
        float4 v  = u[c4];
        float4 sc = ((const float4*)(g_bn + 3 * 128))[c4];
        float4 sh = ((const float4*)(g_bn + 3 * 128 + 64))[c4];
        float4 w  = ((const float4*)Wp)[c4];
        acc = fmaf(fmaxf(fmaf(v.x, sc.x, sh.x), 0.f), w.x, acc);
        acc = fmaf(fmaxf(fmaf(v.y, sc.y, sh.y), 0.f), w.y, acc);
        acc = fmaf(fmaxf(fmaf(v.z, sc.z, sh.z), 0.f), w.z, acc);
        acc = fmaf(fmaxf(fmaf(v.w, sc.w, sh.w), 0.f), w.w, acc);
    }
    out[n] = acc;
}

// ---------------- launch ----------------
extern "C" void kernel_launch(void* const* d_in, const int* in_sizes, int n_in,
                              void* d_out, int out_size) {
    const float* pos = (const float*)d_in[0];
    const float* vel = (const float*)d_in[1];
    const void*  ei  = d_in[2];
    const float* Win = (const float*)d_in[3];
    const float* bin = (const float*)d_in[4];
    const float* mW1 = (const float*)d_in[5];
    const float* mb1 = (const float*)d_in[6];
    const float* mg1 = (const float*)d_in[7];
    const float* mB1 = (const float*)d_in[8];
    const float* mW2 = (const float*)d_in[9];
    const float* mb2 = (const float*)d_in[10];
    const float* mg2 = (const float*)d_in[11];
    const float* mB2 = (const float*)d_in[12];
    const float* uW1 = (const float*)d_in[13];
    const float* ub1 = (const float*)d_in[14];
    const float* ug1 = (const float*)d_in[15];
    const float* uB1 = (const float*)d_in[16];
    const float* uW2 = (const float*)d_in[17];
    const float* ub2 = (const float*)d_in[18];
    const float* ug2 = (const float*)d_in[19];
    const float* uB2 = (const float*)d_in[20];
    const float* Wp  = (const float*)d_in[21];
    const float* bp  = (const float*)d_in[22];
    float* out = (float*)d_out;

    static bool attr_set = false;
    if (!attr_set) {
        cudaFuncSetAttribute(k_edge_fused, cudaFuncAttributeMaxDynamicSharedMemorySize, SMEM_FUSED);
        attr_set = true;
    }

    float *pH, *pP, *pQ, *pAg, *pStat, *pBn;
    __half *pP16, *pQ16;
    cudaGetSymbolAddress((void**)&pH, g_h);
    cudaGetSymbolAddress((void**)&pP, g_P);
    cudaGetSymbolAddress((void**)&pQ, g_Q);
    cudaGetSymbolAddress((void**)&pP16, g_P16);
    cudaGetSymbolAddress((void**)&pQ16, g_Q16);
    cudaGetSymbolAddress((void**)&pAg, g_aggr);
    cudaGetSymbolAddress((void**)&pStat, g_stat);
    cudaGetSymbolAddress((void**)&pBn, g_bn);

    cudaMemsetAsync(pAg, 0, (size_t)NN * EMB * sizeof(float));
    cudaMemsetAsync(pStat, 0, 4 * 2 * EMB * sizeof(float));

    const int GN = (NN + 127) / 128;

    k_detect<<<1, 256>>>((const unsigned int*)ei);
    k_node_embed<<<(NN + 255) / 256, 256>>>(pos, vel, Win, bin);

    // P16 = h @ mW1_top ; Q16 = h @ mW1_bot  (fp16 only — sole edge-phase inputs)
    k_gemm64<false, false, false, false, true, false><<<GN, 256>>>(pH, mW1, nullptr, nullptr, nullptr, nullptr, pP16, nullptr, NN);
    k_gemm64<false, false, false, false, true, false><<<GN, 256>>>(pH, mW1 + 64 * 64, nullptr, nullptr, nullptr, nullptr, pQ16, nullptr, NN);

    // BN1 stats from fp16 P/Q, finalize with mb1 folded into shift
    k_edge_stats1<<<EDGE_GRID, 256>>>(ei, mb1);
    k_finalize<<<1, 64>>>(0, 1.0f / (float)NE, mg1, mB1, mb1);

    // fused: X2(fp16) = relu(bn1'(P16[dst]+Q16[src])) @ mW2 + mb2 (mma.sync fp16) + BN2 stats
    k_edge_fused<<<FUSED_GRID, 256, SMEM_FUSED>>>(ei, mW2, mb2);
    k_finalize<<<1, 64>>>(1, 1.0f / (float)NE, mg2, mB2, nullptr);

    // aggr = segment_sum(relu(bn2(X2)), dst)
    k_edge_scatter<<<EDGE_GRID, 256>>>(ei);

    // update MLP layer 1: T1 = h @ uW1_top + aggr @ uW1_bot + ub1, BN3 stats
    k_gemm64<false, false, false, false, false, true><<<GN, 256>>>(pH, uW1, nullptr, nullptr, nullptr, pP, nullptr, nullptr, NN);
    k_gemm64<false, true, true, true, false, true><<<GN, 256>>>(pAg, uW1 + 64 * 64, ub1, nullptr, nullptr, pP, nullptr, pStat + 256, NN);
    k_finalize<<<1, 64>>>(2, 1.0f / (float)NN, ug1, uB1, nullptr);

    // update MLP layer 2: U2 = relu(bn3(T1)) @ uW2 + ub2, BN4 stats
    k_gemm64<true, false, true, true, false, true><<<GN, 256>>>(pP, uW2, ub2, pBn + 256, pBn + 256 + 64, pQ, nullptr, pStat + 384, NN);
    k_finalize<<<1, 64>>>(3, 1.0f / (float)NN, ug2, uB2, nullptr);

    // out = relu(bn4(U2)) @ W_pred + b_pred
    k_pred<<<(NN + 255) / 256, 256>>>(Wp, bp, out);
}